// round 17
// baseline (speedup 1.0000x reference)
#include <cuda_runtime.h>
#include <math.h>

// Problem constants
#define Bc 32
#define Sc 1024
#define Ec 256
#define Hc 256
#define NCTA 128      // 64 CTAs per direction, 4 hidden units each
#define TPB 256       // 8 warps
#define NPAR 8        // parity depth of the h/s exchange buffers
#define PSTR 536      // per-warp PRED stride (16 cols x 33 + pad)

// Output section offsets (floats)
#define OUT_C 16777216UL          // S*B*2H
#define OUT_S 33554432UL          // 2 * S*B*2H

// SMEM layout (float offsets)
#define OFF_WA   0        // [16 cols][772]  z weights (x|h|s on k)
#define OFF_WB   12352    // [8 cols][516]   r weights (x|h on k)
#define OFF_BA   16480    // [16]
#define OFF_BB   16496    // [16]
#define OFF_SIN  16512    // [32 b][260]     x staging
#define OFF_PRED 24832    // [8 warps][PSTR] k-split partials (col stride 33)
#define OFF_CLOC 29120    // [2 g][4 jj][16 b]
#define OFF_SLOC 29248    // [2 g][8 c][16 b]
#define OFF_HTMP 29504    // [2 g][4 jj][16 b]
#define OFF_MASKW 29632   // [8 warps][32]
#define SMEM_FLOATS 29888
#define SMEM_BYTES (SMEM_FLOATS * 4)

// Exchange buffers, NPAR-deep. [par][dir][b][j]; group A rows 0-15, B rows 16-31.
__device__ float g_h[NPAR * 2 * Bc * Hc];
__device__ float g_s[NPAR * 2 * Bc * Hc];
// Per-group epoch flags, one 32B-padded word per CTA.
__device__ unsigned g_flagsA[NCTA * 8];
__device__ unsigned g_flagsB[NCTA * 8];

__global__ void init_kernel() {
    int tid = blockIdx.x * blockDim.x + threadIdx.x;
    int stride = gridDim.x * blockDim.x;
    for (int i = tid; i < NPAR * 2 * Bc * Hc; i += stride) { g_h[i] = 0.0f; g_s[i] = 0.0f; }
    for (int i = tid; i < NCTA * 8; i += stride) { g_flagsA[i] = 0u; g_flagsB[i] = 0u; }
}

__device__ __forceinline__ float sigf(float x) {
    return __fdividef(1.0f, 1.0f + __expf(-x));
}
__device__ __forceinline__ float tanhf_fast(float x) {
    return 1.0f - __fdividef(2.0f, __expf(2.0f * x) + 1.0f);
}

__device__ __forceinline__ void fma2(unsigned long long& d,
                                     const unsigned long long a,
                                     const unsigned long long b) {
    asm("fma.rn.f32x2 %0, %1, %2, %0;" : "+l"(d) : "l"(a), "l"(b));
}
__device__ __forceinline__ float pair_sum(unsigned long long v) {
    float lo = __uint_as_float((unsigned int)(v & 0xffffffffULL));
    float hi = __uint_as_float((unsigned int)(v >> 32));
    return lo + hi;
}

__device__ __forceinline__ void cp16(const float* smem_ptr, const float* gptr) {
    unsigned sa = (unsigned)__cvta_generic_to_shared(smem_ptr);
    asm volatile("cp.async.cg.shared.global [%0], [%1], 16;" :: "r"(sa), "l"(gptr));
}
__device__ __forceinline__ void cp4(const float* smem_ptr, const float* gptr) {
    unsigned sa = (unsigned)__cvta_generic_to_shared(smem_ptr);
    asm volatile("cp.async.ca.shared.global [%0], [%1], 4;" :: "r"(sa), "l"(gptr));
}
#define CP_COMMIT asm volatile("cp.async.commit_group;")
#define CP_WAIT0  asm volatile("cp.async.wait_group 0;")

// Warp-local producer wait on a given flag array (R10-proven form).
__device__ __forceinline__ void wait_producers(const unsigned* flags, int dir,
                                               int warp, int lane, unsigned e) {
    const unsigned* fp = &flags[(unsigned)(dir * 64 + warp * 8 + (lane & 7)) * 8];
    unsigned v;
    do {
        asm volatile("ld.acquire.gpu.u32 %0, [%1];" : "=r"(v) : "l"(fp) : "memory");
    } while (!__all_sync(0xffffffffu, v >= e));
}
__device__ __forceinline__ void flag_release(unsigned* flags, int cta, unsigned e) {
    unsigned* f = &flags[(unsigned)cta * 8];
    asm volatile("st.release.gpu.u32 [%0], %1;" :: "l"(f), "r"(e) : "memory");
}

// Accumulate a 16-k segment, SMEM input: NC cols, weight row stride WSTR.
template<int NC, int WSTR>
__device__ __forceinline__ void accum_sm16(const float* __restrict__ sm,
                                           unsigned long long* acc,
                                           int in_base, int w_base) {
    const float* inb = sm + in_base;
    const float* wb  = sm + w_base;
    #pragma unroll
    for (int kb = 0; kb < 4; ++kb) {
        ulonglong2 xv = *reinterpret_cast<const ulonglong2*>(inb + kb * 4);
        #pragma unroll
        for (int c = 0; c < NC; ++c) {
            ulonglong2 wv = *reinterpret_cast<const ulonglong2*>(wb + c * WSTR + kb * 4);
            fma2(acc[c], xv.x, wv.x);
            fma2(acc[c], xv.y, wv.y);
        }
    }
}
// Accumulate a 16-k segment, register input (4 x ulonglong2).
template<int NC, int WSTR>
__device__ __forceinline__ void accum_rg16(const float* __restrict__ sm,
                                           unsigned long long* acc,
                                           const ulonglong2* __restrict__ xr,
                                           int w_base) {
    const float* wb = sm + w_base;
    #pragma unroll
    for (int kb = 0; kb < 4; ++kb) {
        #pragma unroll
        for (int c = 0; c < NC; ++c) {
            ulonglong2 wv = *reinterpret_cast<const ulonglong2*>(wb + c * WSTR + kb * 4);
            fma2(acc[c], xr[kb].x, wv.x);
            fma2(acc[c], xr[kb].y, wv.y);
        }
    }
}

__global__ void __launch_bounds__(TPB, 1) bislstm_kernel(
    const float* __restrict__ inputs, const float* __restrict__ mask,
    const float* __restrict__ Wx,   const float* __restrict__ Wh,
    const float* __restrict__ Ws,   const float* __restrict__ bz,
    const float* __restrict__ Wrx,  const float* __restrict__ Wrh,
    const float* __restrict__ br,
    const float* __restrict__ Wx_r, const float* __restrict__ Wh_r,
    const float* __restrict__ Ws_r, const float* __restrict__ bz_r,
    const float* __restrict__ Wrx_r,const float* __restrict__ Wrh_r,
    const float* __restrict__ br_r,
    const int* __restrict__ idx_ptr, float* __restrict__ out)
{
    extern __shared__ float sm[];
    const int tid  = threadIdx.x;
    const int warp = tid >> 5;
    const int lane = tid & 31;
    const int sub  = lane >> 4;          // k-half within warp slice
    const int bl   = lane & 15;          // batch-local (within group)
    const int cta  = blockIdx.x;
    const int dir  = cta >> 6;
    const int cid  = cta & 63;
    const int jbase = cid * 4;
    const int idxv = *idx_ptr;
    const int w32  = warp * 32;
    const int koff = w32 + sub * 16;     // lane's k-offset inside each 256-segment

    const float* pWx  = dir ? Wx_r  : Wx;
    const float* pWh  = dir ? Wh_r  : Wh;
    const float* pWs  = dir ? Ws_r  : Ws;
    const float* pB   = dir ? bz_r  : bz;
    const float* pWrx = dir ? Wrx_r : Wrx;
    const float* pWrh = dir ? Wrh_r : Wrh;
    const float* pBr  = dir ? br_r  : br;

    // ---- Load weight slices into SMEM (once) ----
    for (int i = tid; i < 16 * 768; i += TPB) {
        int k = i >> 4, c = i & 15;
        int gate = c >> 2, jj = c & 3;
        int gcol = gate * Hc + jbase + jj;
        float v;
        if (k < 256)      v = pWx[(size_t)k * (4 * Hc) + gcol];
        else if (k < 512) v = pWh[(size_t)(k - 256) * (4 * Hc) + gcol];
        else              v = pWs[(size_t)(k - 512) * (4 * Hc) + gcol];
        sm[OFF_WA + c * 772 + k] = v;
    }
    for (int i = tid; i < 8 * 512; i += TPB) {
        int k = i >> 3, c = i & 7;
        int kk = c >> 2, jj = c & 3;
        int j = jbase + jj;
        float v;
        if (k < 256) v = pWrx[(size_t)kk * Ec * Hc + (size_t)k * Hc + j];
        else         v = pWrh[(size_t)kk * Hc * Hc + (size_t)(k - 256) * Hc + j];
        sm[OFF_WB + c * 516 + k] = v;
    }
    if (tid < 16) {
        int gate = tid >> 2, jj = tid & 3;
        sm[OFF_BA + tid] = pB[gate * Hc + jbase + jj];
    }
    if (tid < 8) {
        int kk = tid >> 2, jj = tid & 3;
        sm[OFF_BB + tid] = pBr[kk * Hc + jbase + jj];
    }
    if (tid < 128) { sm[OFF_CLOC + tid] = 0.0f; sm[OFF_HTMP + tid] = 0.0f; }
    sm[OFF_SLOC + tid] = 0.0f;

    // prefetch x_0 / mask_0 (lane copies row=lane, warp's 32-col slice)
    {
        const int t0 = dir ? (Sc - 1) : 0;
        const float* xrow = inputs + ((size_t)lane * Sc + t0) * Ec + w32;
        #pragma unroll
        for (int j = 0; j < 8; ++j)
            cp16(&sm[OFF_SIN + lane * 260 + w32 + j * 4], xrow + j * 4);
        cp4(&sm[OFF_MASKW + warp * 32 + lane], mask + (size_t)lane * Sc + t0);
        CP_COMMIT; CP_WAIT0;
    }
    __syncthreads();

    // z partial accumulators per group (x + h parts carried across superstep)
    unsigned long long acc2A[16], acc2B[16];
    #pragma unroll
    for (int c = 0; c < 16; ++c) { acc2A[c] = 0ULL; acc2B[c] = 0ULL; }
    // prologue: x-parts of step 0
    accum_sm16<16, 772>(sm, acc2A, OFF_SIN + bl * 260 + koff,        OFF_WA + koff);
    accum_sm16<16, 772>(sm, acc2B, OFF_SIN + (16 + bl) * 260 + koff, OFF_WA + koff);
    // prologue: s_{-1} = 0 (slot 7 is zeroed)
    ulonglong2 sregA[4], sregB[4];
    {
        const float* sA = g_s + ((size_t)(NPAR - 1) * 2 + dir) * (Bc * Hc) + bl * 256 + koff;
        const float* sB = g_s + ((size_t)(NPAR - 1) * 2 + dir) * (Bc * Hc) + (16 + bl) * 256 + koff;
        #pragma unroll
        for (int j = 0; j < 4; ++j) {
            sregA[j] = __ldcg(reinterpret_cast<const ulonglong2*>(sA + j * 4));
            sregB[j] = __ldcg(reinterpret_cast<const ulonglong2*>(sB + j * 4));
        }
    }

    unsigned long long accR[8];
    ulonglong2 hregA[4], hregB[4];

    for (int n = 0; n < Sc; ++n) {
        const int t = dir ? (Sc - 1 - n) : n;
        const int wpar = n & (NPAR - 1);
        const size_t slot = ((size_t)wpar * 2 + dir) * (Bc * Hc);

        // ================= group A, phase a =================
        accum_rg16<16, 772>(sm, acc2A, sregA, OFF_WA + 512 + koff);
        #pragma unroll
        for (int c = 0; c < 16; ++c)
            sm[OFF_PRED + warp * PSTR + c * 33 + lane] = pair_sum(acc2A[c]);
        __syncthreads();
        if (tid < 64) {   // gates A (g=0)
            const int jj = tid >> 4, b2 = tid & 15;
            float zi = sm[OFF_BA + jj],     zf = sm[OFF_BA + 4 + jj];
            float zg = sm[OFF_BA + 8 + jj], zo = sm[OFF_BA + 12 + jj];
            #pragma unroll
            for (int w = 0; w < 8; ++w) {
                const float* p = &sm[OFF_PRED + w * PSTR + b2];
                zi += p[jj * 33]        + p[jj * 33 + 16];
                zf += p[(jj + 4) * 33]  + p[(jj + 4) * 33 + 16];
                zg += p[(jj + 8) * 33]  + p[(jj + 8) * 33 + 16];
                zo += p[(jj + 12) * 33] + p[(jj + 12) * 33 + 16];
            }
            const int si = jj * 16 + b2;
            const float cold = sm[OFF_CLOC + si];
            const float hold = sm[OFF_HTMP + si];
            const float m    = sm[OFF_MASKW + (tid >> 5) * 32 + b2];
            const float cn = sigf(zf) * cold + sigf(zi) * tanhf_fast(zg);
            const float hn = sigf(zo) * tanhf_fast(cn);
            sm[OFF_HTMP + si] = m * hn + (1.0f - m) * hold;
            sm[OFF_CLOC + si] = m * cn + (1.0f - m) * cold;
        }
        __syncthreads();
        if (tid < 32) {   // publish hA + outputs, release A(2n+1)
            if (tid < 16) {
                const int b2 = tid;
                float4 hv = make_float4(sm[OFF_HTMP + b2],      sm[OFF_HTMP + 16 + b2],
                                        sm[OFF_HTMP + 32 + b2], sm[OFF_HTMP + 48 + b2]);
                float4 cv = make_float4(sm[OFF_CLOC + b2],      sm[OFF_CLOC + 16 + b2],
                                        sm[OFF_CLOC + 32 + b2], sm[OFF_CLOC + 48 + b2]);
                *reinterpret_cast<float4*>(g_h + slot + b2 * 256 + jbase) = hv;
                size_t ob = (size_t)t * (Bc * 512) + (size_t)b2 * 512 + dir * 256 + jbase;
                *reinterpret_cast<float4*>(out + ob) = hv;
                *reinterpret_cast<float4*>(out + OUT_C + ob) = cv;
            }
            __syncwarp();
            if (tid == 0) flag_release(g_flagsA, cta, 2u * n + 1u);
        }

        // ================= group B, phase a =================
        accum_rg16<16, 772>(sm, acc2B, sregB, OFF_WA + 512 + koff);
        #pragma unroll
        for (int c = 0; c < 16; ++c)
            sm[OFF_PRED + warp * PSTR + c * 33 + lane] = pair_sum(acc2B[c]);
        __syncthreads();
        if (tid < 64) {   // gates B (g=1)
            const int jj = tid >> 4, b2 = tid & 15;
            float zi = sm[OFF_BA + jj],     zf = sm[OFF_BA + 4 + jj];
            float zg = sm[OFF_BA + 8 + jj], zo = sm[OFF_BA + 12 + jj];
            #pragma unroll
            for (int w = 0; w < 8; ++w) {
                const float* p = &sm[OFF_PRED + w * PSTR + b2];
                zi += p[jj * 33]        + p[jj * 33 + 16];
                zf += p[(jj + 4) * 33]  + p[(jj + 4) * 33 + 16];
                zg += p[(jj + 8) * 33]  + p[(jj + 8) * 33 + 16];
                zo += p[(jj + 12) * 33] + p[(jj + 12) * 33 + 16];
            }
            const int si = 64 + jj * 16 + b2;
            const float cold = sm[OFF_CLOC + si];
            const float hold = sm[OFF_HTMP + si];
            const float m    = sm[OFF_MASKW + (tid >> 5) * 32 + 16 + b2];
            const float cn = sigf(zf) * cold + sigf(zi) * tanhf_fast(zg);
            const float hn = sigf(zo) * tanhf_fast(cn);
            sm[OFF_HTMP + si] = m * hn + (1.0f - m) * hold;
            sm[OFF_CLOC + si] = m * cn + (1.0f - m) * cold;
        }
        __syncthreads();
        if (tid < 32) {   // publish hB + outputs, release B(2n+1)
            if (tid < 16) {
                const int b2 = tid;
                float4 hv = make_float4(sm[OFF_HTMP + 64 + b2],  sm[OFF_HTMP + 80 + b2],
                                        sm[OFF_HTMP + 96 + b2],  sm[OFF_HTMP + 112 + b2]);
                float4 cv = make_float4(sm[OFF_CLOC + 64 + b2],  sm[OFF_CLOC + 80 + b2],
                                        sm[OFF_CLOC + 96 + b2],  sm[OFF_CLOC + 112 + b2]);
                *reinterpret_cast<float4*>(g_h + slot + (16 + b2) * 256 + jbase) = hv;
                size_t ob = (size_t)t * (Bc * 512) + (size_t)(16 + b2) * 512 + dir * 256 + jbase;
                *reinterpret_cast<float4*>(out + ob) = hv;
                *reinterpret_cast<float4*>(out + OUT_C + ob) = cv;
            }
            __syncwarp();
            if (tid == 0) flag_release(g_flagsB, cta, 2u * n + 1u);
        }

        // ================= group A, phase b =================
        #pragma unroll
        for (int c = 0; c < 8; ++c) accR[c] = 0ULL;
        accum_sm16<8, 516>(sm, accR, OFF_SIN + bl * 260 + koff, OFF_WB + koff);
        wait_producers(g_flagsA, dir, warp, lane, 2u * n + 1u);
        {
            const float* hsrc = g_h + slot + bl * 256 + koff;
            #pragma unroll
            for (int j = 0; j < 4; ++j)
                hregA[j] = __ldcg(reinterpret_cast<const ulonglong2*>(hsrc + j * 4));
        }
        accum_rg16<8, 516>(sm, accR, hregA, OFF_WB + 256 + koff);
        #pragma unroll
        for (int c = 0; c < 8; ++c)
            sm[OFF_PRED + warp * PSTR + c * 33 + lane] = pair_sum(accR[c]);
        __syncthreads();
        if (tid < 128) {  // s update A
            const int c = tid >> 4, b2 = tid & 15;
            const int jj = c & 3;
            float z = sm[OFF_BB + c];
            #pragma unroll
            for (int w = 0; w < 8; ++w) {
                const float* p = &sm[OFF_PRED + w * PSTR + c * 33 + b2];
                z += p[0] + p[16];
            }
            const float r    = sigf(z);
            const float sold = sm[OFF_SLOC + c * 16 + b2];
            const float cc   = sm[OFF_CLOC + jj * 16 + b2];
            const float m    = sm[OFF_MASKW + (tid >> 5) * 32 + b2];
            const float sn   = r * sold + (1.0f - r) * cc;
            sm[OFF_SLOC + c * 16 + b2] = m * sn + (1.0f - m) * sold;
        }
        __syncthreads();
        if (tid < 32) {   // publish sA[idx] + s outputs, release A(2n+2)
            if (tid < 16) {
                const int b2 = tid;
                const int ib = idxv * 64 + b2;
                float4 siv = make_float4(sm[OFF_SLOC + ib],      sm[OFF_SLOC + ib + 16],
                                         sm[OFF_SLOC + ib + 32], sm[OFF_SLOC + ib + 48]);
                *reinterpret_cast<float4*>(g_s + slot + b2 * 256 + jbase) = siv;
                #pragma unroll
                for (int kk = 0; kk < 2; ++kk) {
                    const int base = kk * 64 + b2;
                    float4 sv = make_float4(sm[OFF_SLOC + base],      sm[OFF_SLOC + base + 16],
                                            sm[OFF_SLOC + base + 32], sm[OFF_SLOC + base + 48]);
                    size_t ob = (size_t)kk * ((size_t)Sc * Bc * 512)
                              + (size_t)t * (Bc * 512) + (size_t)b2 * 512 + dir * 256 + jbase;
                    *reinterpret_cast<float4*>(out + OUT_S + ob) = sv;
                }
            }
            __syncwarp();
            if (tid == 0) flag_release(g_flagsA, cta, 2u * n + 2u);
        }

        // ================= group B, phase b =================
        #pragma unroll
        for (int c = 0; c < 8; ++c) accR[c] = 0ULL;
        accum_sm16<8, 516>(sm, accR, OFF_SIN + (16 + bl) * 260 + koff, OFF_WB + koff);
        wait_producers(g_flagsB, dir, warp, lane, 2u * n + 1u);
        {
            const float* hsrc = g_h + slot + (16 + bl) * 256 + koff;
            #pragma unroll
            for (int j = 0; j < 4; ++j)
                hregB[j] = __ldcg(reinterpret_cast<const ulonglong2*>(hsrc + j * 4));
        }
        accum_rg16<8, 516>(sm, accR, hregB, OFF_WB + 256 + koff);
        #pragma unroll
        for (int c = 0; c < 8; ++c)
            sm[OFF_PRED + warp * PSTR + c * 33 + lane] = pair_sum(accR[c]);
        __syncthreads();
        if (tid < 128) {  // s update B
            const int c = tid >> 4, b2 = tid & 15;
            const int jj = c & 3;
            float z = sm[OFF_BB + c];
            #pragma unroll
            for (int w = 0; w < 8; ++w) {
                const float* p = &sm[OFF_PRED + w * PSTR + c * 33 + b2];
                z += p[0] + p[16];
            }
            const float r    = sigf(z);
            const float sold = sm[OFF_SLOC + 128 + c * 16 + b2];
            const float cc   = sm[OFF_CLOC + 64 + jj * 16 + b2];
            const float m    = sm[OFF_MASKW + (tid >> 5) * 32 + 16 + b2];
            const float sn   = r * sold + (1.0f - r) * cc;
            sm[OFF_SLOC + 128 + c * 16 + b2] = m * sn + (1.0f - m) * sold;
        }
        __syncthreads();
        if (tid < 32) {   // publish sB[idx] + s outputs, release B(2n+2)
            if (tid < 16) {
                const int b2 = tid;
                const int ib = 128 + idxv * 64 + b2;
                float4 siv = make_float4(sm[OFF_SLOC + ib],      sm[OFF_SLOC + ib + 16],
                                         sm[OFF_SLOC + ib + 32], sm[OFF_SLOC + ib + 48]);
                *reinterpret_cast<float4*>(g_s + slot + (16 + b2) * 256 + jbase) = siv;
                #pragma unroll
                for (int kk = 0; kk < 2; ++kk) {
                    const int base = 128 + kk * 64 + b2;
                    float4 sv = make_float4(sm[OFF_SLOC + base],      sm[OFF_SLOC + base + 16],
                                            sm[OFF_SLOC + base + 32], sm[OFF_SLOC + base + 48]);
                    size_t ob = (size_t)kk * ((size_t)Sc * Bc * 512)
                              + (size_t)t * (Bc * 512) + (size_t)(16 + b2) * 512 + dir * 256 + jbase;
                    *reinterpret_cast<float4*>(out + OUT_S + ob) = sv;
                }
            }
            __syncwarp();
            if (tid == 0) flag_release(g_flagsB, cta, 2u * n + 2u);
        }

        // ================= tail: prep superstep n+1 =================
        if (n + 1 < Sc) {
            __syncwarp();   // warp-local x reads complete before overwrite
            const int tn = dir ? (Sc - 2 - n) : (n + 1);
            const float* xrow = inputs + ((size_t)lane * Sc + tn) * Ec + w32;
            #pragma unroll
            for (int j = 0; j < 8; ++j)
                cp16(&sm[OFF_SIN + lane * 260 + w32 + j * 4], xrow + j * 4);
            cp4(&sm[OFF_MASKW + warp * 32 + lane], mask + (size_t)lane * Sc + tn);
            CP_COMMIT;

            // z h-parts for n+1 (from registers; hides prefetch latency)
            #pragma unroll
            for (int c = 0; c < 16; ++c) { acc2A[c] = 0ULL; acc2B[c] = 0ULL; }
            accum_rg16<16, 772>(sm, acc2A, hregA, OFF_WA + 256 + koff);
            accum_rg16<16, 772>(sm, acc2B, hregB, OFF_WA + 256 + koff);

            CP_WAIT0;
            __syncwarp();   // peer-lane x copies in this warp's columns visible
            accum_sm16<16, 772>(sm, acc2A, OFF_SIN + bl * 260 + koff,        OFF_WA + koff);
            accum_sm16<16, 772>(sm, acc2B, OFF_SIN + (16 + bl) * 260 + koff, OFF_WA + koff);

            // s_{n} waits + loads (released this superstep; settled by now)
            const size_t rslot = slot;   // step n wrote slot wpar; consumer of n+1 reads it
            wait_producers(g_flagsA, dir, warp, lane, 2u * n + 2u);
            {
                const float* sA = g_s + rslot + bl * 256 + koff;
                #pragma unroll
                for (int j = 0; j < 4; ++j)
                    sregA[j] = __ldcg(reinterpret_cast<const ulonglong2*>(sA + j * 4));
            }
            wait_producers(g_flagsB, dir, warp, lane, 2u * n + 2u);
            {
                const float* sB = g_s + rslot + (16 + bl) * 256 + koff;
                #pragma unroll
                for (int j = 0; j < 4; ++j)
                    sregB[j] = __ldcg(reinterpret_cast<const ulonglong2*>(sB + j * 4));
            }
        }
    }
}

extern "C" void kernel_launch(void* const* d_in, const int* in_sizes, int n_in,
                              void* d_out, int out_size) {
    (void)in_sizes; (void)n_in; (void)out_size;
    cudaFuncSetAttribute(bislstm_kernel,
                         cudaFuncAttributeMaxDynamicSharedMemorySize, SMEM_BYTES);
    init_kernel<<<64, 256>>>();
    bislstm_kernel<<<NCTA, TPB, SMEM_BYTES>>>(
        (const float*)d_in[0],  (const float*)d_in[1],
        (const float*)d_in[2],  (const float*)d_in[3],
        (const float*)d_in[4],  (const float*)d_in[5],
        (const float*)d_in[6],  (const float*)d_in[7],
        (const float*)d_in[8],
        (const float*)d_in[9],  (const float*)d_in[10],
        (const float*)d_in[11], (const float*)d_in[12],
        (const float*)d_in[13], (const float*)d_in[14],
        (const float*)d_in[15],
        (const int*)d_in[16],   (float*)d_out);
}